// round 10
// baseline (speedup 1.0000x reference)
#include <cuda_runtime.h>
#include <cuda_fp16.h>
#include <cstdint>

// ---------------------------------------------------------------------------
// Problem constants
// ---------------------------------------------------------------------------
#define B_DIM 32
#define W_DIM 16
#define N_DIM 256

// Wgh[w][s][m][n] fp16 weights (8.4 MB), L2-resident.
__device__ __half g_Wgh[W_DIM * 4 * N_DIM * N_DIM];

// ---------------------------------------------------------------------------
// Kernel 1: Wgh[w][s][m][n] = fp16(bias_table[rel_index[m][n], s*16+w])
// ---------------------------------------------------------------------------
__global__ __launch_bounds__(256) void build_weights(
    const float* __restrict__ bias_table, const int* __restrict__ rel_index)
{
    __shared__ float tile[128][65];
    __shared__ int rels[128];
    const int m  = blockIdx.x;
    const int n0 = blockIdx.y * 128;
    const int tid = threadIdx.x;

    if (tid < 128) rels[tid] = rel_index[m * N_DIM + n0 + tid];
    __syncthreads();

#pragma unroll
    for (int i = 0; i < 32; i++) {
        int u = tid + i * 256;
        int n = u >> 6, c = u & 63;
        tile[n][c] = bias_table[rels[n] * 64 + c];
    }
    __syncthreads();

    __half2* g2 = reinterpret_cast<__half2*>(g_Wgh);
#pragma unroll
    for (int i = 0; i < 16; i++) {
        int u = tid + i * 256;
        int c = u >> 6, n2 = u & 63;
        int wq = c & 15, s = c >> 4;
        g2[(((wq * 4 + s) * N_DIM + m) << 7) + (n0 >> 1) + n2] =
            __floats2half2_rn(tile[2 * n2][c], tile[2 * n2 + 1][c]);
    }
}

// ---------------------------------------------------------------------------
// MMA / ldmatrix helpers
// ---------------------------------------------------------------------------
__device__ __forceinline__ void ldsm_x4(uint32_t* r, uint32_t addr) {
    asm volatile("ldmatrix.sync.aligned.m8n8.x4.shared.b16 {%0,%1,%2,%3}, [%4];"
        : "=r"(r[0]), "=r"(r[1]), "=r"(r[2]), "=r"(r[3]) : "r"(addr));
}
__device__ __forceinline__ void ldsm_x4_t(uint32_t* r, uint32_t addr) {
    asm volatile("ldmatrix.sync.aligned.m8n8.x4.trans.shared.b16 {%0,%1,%2,%3}, [%4];"
        : "=r"(r[0]), "=r"(r[1]), "=r"(r[2]), "=r"(r[3]) : "r"(addr));
}
__device__ __forceinline__ void hmma(float* d, const uint32_t* a, uint32_t b0, uint32_t b1) {
    asm volatile(
        "mma.sync.aligned.m16n8k16.row.col.f32.f16.f16.f32 "
        "{%0,%1,%2,%3},{%4,%5,%6,%7},{%8,%9},{%0,%1,%2,%3};"
        : "+f"(d[0]), "+f"(d[1]), "+f"(d[2]), "+f"(d[3])
        : "r"(a[0]), "r"(a[1]), "r"(a[2]), "r"(a[3]), "r"(b0), "r"(b1));
}
__device__ __forceinline__ uint32_t pack_h2(float lo, float hi) {
    __half2 h = __floats2half2_rn(lo, hi);
    return *reinterpret_cast<uint32_t*>(&h);
}
__device__ __forceinline__ uint32_t smem_u32(const void* p) {
    uint32_t a;
    asm("{ .reg .u64 t; cvta.to.shared.u64 t, %1; cvt.u32.u64 %0, t; }"
        : "=r"(a) : "l"(p));
    return a;
}

// ---------------------------------------------------------------------------
// Main kernel: CTA = bx -> (sp = bx&1, mh = (bx>>1)&1, w = (bx>>2)&15,
// b = bx>>6).  OUT tile M=128 x 128 cols (2 s-planes x 64 v).
// 256 threads / 8 warps (4 m-groups x 2 s), warp tile 32m x 64v.
// __launch_bounds__(256, 2) -> 2 CTAs/SM: one CTA's prologue/barriers overlap
// the sibling CTA's compute. Grid order keeps the 4 CTAs of a (b,w) window
// wave-adjacent so split x sectors / shared A rows hit L2.
// X: resident smem [s'][256k][64v] fp16 (rows 128B, swizzle c ^= k&7), 64 KB,
//    filled once in the prologue (overlapped with A chunk 0 cp.async).
// A: K chunks of 32, double-buffered cp.async [s'][128m][32k] fp16
//    (rows 64B, swizzle q ^= (m>>1)&3) -- 2 x 16 KB.  Total 96 KB/CTA.
// ---------------------------------------------------------------------------
#define AS_PLANE 8192
#define A_STAGE  16384
#define X_BASE   (2 * A_STAGE)               // 32768
#define XS_PLANE 32768
#define OUT_PITCH 130
#define SMEM_DYN (X_BASE + 2 * XS_PLANE)     // 98304 (2 CTAs = 192 KB/SM)

__global__ __launch_bounds__(256, 2) void pos_map_mm(
    const float* __restrict__ x, const float* __restrict__ token_bias,
    float* __restrict__ out)
{
    extern __shared__ __align__(16) char smem[];
    const int bx = blockIdx.x;
    const int sp = bx & 1, m0 = ((bx >> 1) & 1) * 128;
    const int w = (bx >> 2) & 15, b = bx >> 6;
    const int tid = threadIdx.x, lane = tid & 31, warp = tid >> 5;
    const int wm = warp & 3;    // m-group: 32 rows
    const int wc = warp >> 2;   // s' within pair: 0/1
    const uint32_t sbase = smem_u32(smem);

    const __half* WgBase = g_Wgh + (size_t)(w * 4 + sp * 2) * 65536
                         + (size_t)m0 * 256;
    const float* xb = x + (size_t)(b * 16 + w) * (256 * 256) + 2 * sp;

    float acc[2][8][4];
#pragma unroll
    for (int mt = 0; mt < 2; mt++)
#pragma unroll
        for (int nt = 0; nt < 8; nt++)
#pragma unroll
            for (int j = 0; j < 4; j++) acc[mt][nt][j] = 0.f;

    const int grp  = lane >> 3;
    const int row8 = (grp & 1) * 8 + (lane & 7);
    const int qsel = grp >> 1;

    auto issue_A = [&](int st, int ch) {
        const int n0c = ch * 32;
#pragma unroll
        for (int i = 0; i < 4; i++) {
            int u = tid + i * 256;                 // 1024 x 16B units
            int s = u >> 9, m = (u >> 2) & 127, q = u & 3;
            const __half* src = WgBase + s * 65536 + m * 256 + n0c + q * 8;
            uint32_t dst = sbase + st * A_STAGE + s * AS_PLANE + m * 64
                         + ((q ^ ((m >> 1) & 3)) << 4);
            asm volatile("cp.async.cg.shared.global [%0], [%1], 16;"
                         :: "r"(dst), "l"(src));
        }
        asm volatile("cp.async.commit_group;");
    };

    // ---- prologue: A chunk 0 in flight; fill resident X (2 s-planes) ----
    issue_A(0, 0);

#pragma unroll
    for (int i = 0; i < 32; i++) {
        int u = tid + i * 256;                 // 8192 units: 256k x 32vp
        int k = u >> 5, vp = u & 31;
        // x[n=k][v=2vp..2vp+1][s=2sp..2sp+1]: two float2 loads
        float2 f0 = *(const float2*)(xb + (size_t)k * 256 + (2 * vp) * 4);
        float2 f1 = *(const float2*)(xb + (size_t)k * 256 + (2 * vp + 1) * 4);
        uint32_t off = X_BASE + (uint32_t)k * 128
                     + (((vp >> 2) ^ (k & 7)) << 4) + ((vp & 3) << 2);
        *(uint32_t*)(smem + off)             = pack_h2(f0.x, f1.x);
        *(uint32_t*)(smem + off + XS_PLANE)  = pack_h2(f0.y, f1.y);
    }

    asm volatile("cp.async.wait_group 0;");
    __syncthreads();

    // ---- main loop: 8 A-chunks of 32 k (fully unrolled) ----
#pragma unroll
    for (int ch = 0; ch < 8; ch++) {
        const int st = ch & 1;
        if (ch < 7) issue_A((ch + 1) & 1, ch + 1);

        const uint32_t sA = sbase + st * A_STAGE + wc * AS_PLANE;
        const uint32_t sX = sbase + X_BASE + wc * XS_PLANE;
#pragma unroll
        for (int ks = 0; ks < 2; ks++) {
            uint32_t a[2][4];
#pragma unroll
            for (int mt = 0; mt < 2; mt++) {
                int m = wm * 32 + mt * 16 + row8;
                int q = ks * 2 + qsel;
                ldsm_x4(a[mt], sA + m * 64 + ((q ^ ((m >> 1) & 3)) << 4));
            }
            uint32_t bq[4][4];
#pragma unroll
            for (int ng = 0; ng < 4; ng++) {
                int k = ch * 32 + ks * 16 + row8;
                int c = ng * 2 + qsel;
                ldsm_x4_t(bq[ng], sX + k * 128 + ((c ^ (k & 7)) << 4));
            }
#pragma unroll
            for (int mt = 0; mt < 2; mt++)
#pragma unroll
                for (int nt = 0; nt < 8; nt++)
                    hmma(acc[mt][nt], a[mt],
                         bq[nt >> 1][(nt & 1) * 2], bq[nt >> 1][(nt & 1) * 2 + 1]);
        }

        asm volatile("cp.async.wait_group 0;");
        __syncthreads();
    }

    // ---- epilogue: bias add, smem stage (reuses A/X region), f2 store ----
    float* so = (float*)smem;   // [128][OUT_PITCH] = 66560 B < SMEM_DYN
#pragma unroll
    for (int mt = 0; mt < 2; mt++)
#pragma unroll
        for (int j = 0; j < 2; j++) {
            int m = wm * 32 + mt * 16 + (lane >> 2) + j * 8;
            float tb = token_bias[(w * 4 + sp * 2 + wc) * 256 + m0 + m];
            float* dr = so + m * OUT_PITCH + wc;
#pragma unroll
            for (int nt = 0; nt < 8; nt++) {
                int v = nt * 8 + ((lane & 3) << 1);
                dr[2 * v]       = acc[mt][nt][j * 2 + 0] + tb;
                dr[2 * (v + 1)] = acc[mt][nt][j * 2 + 1] + tb;
            }
        }
    __syncthreads();

    // out cols for this CTA: d = 4v + 2sp + s' -> float2 at 4v + 2sp
    float* ob = out + (size_t)((b * 16 + w) * 256 + m0) * 256 + 2 * sp;
#pragma unroll
    for (int i = 0; i < 32; i++) {
        int u = tid + i * 256;
        int row = u >> 6, vv = u & 63;
        *(float2*)(ob + row * 256 + 4 * vv) =
            *(float2*)(so + row * OUT_PITCH + 2 * vv);
    }
}

// ---------------------------------------------------------------------------
// Launch: inputs in metadata order: x, bias_table, token_bias, rel_index
// ---------------------------------------------------------------------------
extern "C" void kernel_launch(void* const* d_in, const int* in_sizes, int n_in,
                              void* d_out, int out_size)
{
    const float* x          = (const float*)d_in[0];
    const float* bias_table = (const float*)d_in[1];
    const float* token_bias = (const float*)d_in[2];
    const int*   rel_index  = (const int*)d_in[3];
    float* out = (float*)d_out;
    (void)in_sizes; (void)n_in; (void)out_size;

    cudaFuncSetAttribute(pos_map_mm,
                         cudaFuncAttributeMaxDynamicSharedMemorySize, SMEM_DYN);

    build_weights<<<dim3(256, 2), 256>>>(bias_table, rel_index);
    pos_map_mm<<<2048, 256, SMEM_DYN>>>(x, token_bias, out);
}

// round 13
// speedup vs baseline: 1.0326x; 1.0326x over previous
#include <cuda_runtime.h>
#include <cuda_fp16.h>
#include <cstdint>

// ---------------------------------------------------------------------------
// Problem constants
// ---------------------------------------------------------------------------
#define B_DIM 32
#define W_DIM 16
#define N_DIM 256

// Wgh[w][s][m][n] fp16 weights (8.4 MB) + Xt[b][w][s][n][v] fp16 x (67 MB).
__device__ __half  g_Wgh[W_DIM * 4 * N_DIM * N_DIM];
__device__ __half2 g_Xt2[B_DIM * W_DIM * 4 * N_DIM * 32];

// ---------------------------------------------------------------------------
// Prep kernel: bx < 512 -> fat transpose of one (b, w) x-window to Xt;
//              bx >= 512 -> weight gather (m, n-half) into Wgh.
// 1024 CTAs total: DRAM-bound transposes overlap latency-bound gathers.
// ---------------------------------------------------------------------------
__global__ __launch_bounds__(256) void prep(
    const float* __restrict__ x,
    const float* __restrict__ bias_table, const int* __restrict__ rel_index)
{
    __shared__ float tile[128][65];
    __shared__ int rels[128];
    const int bx = blockIdx.x, tid = threadIdx.x;

    if (bx < 512) {
        // ---- x transpose: CTA = (b, w), full 256n x 256d window ----
        const int w = bx & 15, b = bx >> 4;
        const float4* xb4 = (const float4*)x + (size_t)(b * 16 + w) * (256 * 64);
        __half2* xt = g_Xt2 + (size_t)(b * 16 + w) * 4 * 8192;
#pragma unroll
        for (int i = 0; i < 32; i++) {
            int u = tid + i * 256;             // 8192 units: 256n x 32vp
            int vp = u & 31, n = u >> 5;
            float4 f0 = xb4[n * 64 + 2 * vp];
            float4 f1 = xb4[n * 64 + 2 * vp + 1];
            const float* p0 = reinterpret_cast<const float*>(&f0);
            const float* p1 = reinterpret_cast<const float*>(&f1);
#pragma unroll
            for (int s = 0; s < 4; s++)
                xt[s * 8192 + n * 32 + vp] = __floats2half2_rn(p0[s], p1[s]);
        }
        return;
    }

    // ---- weight build: r = (m, n-half) ----
    const int r = bx - 512;
    const int m = r >> 1, n0 = (r & 1) * 128;

    if (tid < 128) rels[tid] = rel_index[m * N_DIM + n0 + tid];
    __syncthreads();

#pragma unroll
    for (int i = 0; i < 32; i++) {
        int u = tid + i * 256;
        int n = u >> 6, c = u & 63;
        tile[n][c] = bias_table[rels[n] * 64 + c];
    }
    __syncthreads();

    __half2* g2 = reinterpret_cast<__half2*>(g_Wgh);
#pragma unroll
    for (int i = 0; i < 16; i++) {
        int u = tid + i * 256;
        int c = u >> 6, n2 = u & 63;
        int wq = c & 15, s = c >> 4;
        g2[(((wq * 4 + s) * N_DIM + m) << 7) + (n0 >> 1) + n2] =
            __floats2half2_rn(tile[2 * n2][c], tile[2 * n2 + 1][c]);
    }
}

// ---------------------------------------------------------------------------
// MMA / ldmatrix helpers
// ---------------------------------------------------------------------------
__device__ __forceinline__ void ldsm_x4(uint32_t* r, uint32_t addr) {
    asm volatile("ldmatrix.sync.aligned.m8n8.x4.shared.b16 {%0,%1,%2,%3}, [%4];"
        : "=r"(r[0]), "=r"(r[1]), "=r"(r[2]), "=r"(r[3]) : "r"(addr));
}
__device__ __forceinline__ void ldsm_x4_t(uint32_t* r, uint32_t addr) {
    asm volatile("ldmatrix.sync.aligned.m8n8.x4.trans.shared.b16 {%0,%1,%2,%3}, [%4];"
        : "=r"(r[0]), "=r"(r[1]), "=r"(r[2]), "=r"(r[3]) : "r"(addr));
}
__device__ __forceinline__ void hmma(float* d, const uint32_t* a, uint32_t b0, uint32_t b1) {
    asm volatile(
        "mma.sync.aligned.m16n8k16.row.col.f32.f16.f16.f32 "
        "{%0,%1,%2,%3},{%4,%5,%6,%7},{%8,%9},{%0,%1,%2,%3};"
        : "+f"(d[0]), "+f"(d[1]), "+f"(d[2]), "+f"(d[3])
        : "r"(a[0]), "r"(a[1]), "r"(a[2]), "r"(a[3]), "r"(b0), "r"(b1));
}
__device__ __forceinline__ uint32_t smem_u32(const void* p) {
    uint32_t a;
    asm("{ .reg .u64 t; cvta.to.shared.u64 t, %1; cvt.u32.u64 %0, t; }"
        : "=r"(a) : "l"(p));
    return a;
}

// ---------------------------------------------------------------------------
// Main kernel: CTA = bx -> (mh = bx&1, w = (bx>>1)&15, b = bx>>5).
// OUT tile M=128 x D=256. 512 thr. Pure cp.async operands from Wgh/Xt,
// 3-stage pipeline, K chunks of 32, fully unrolled (compile-time ch%3),
// wait_group 1 keeps one group in flight across each barrier.
//   A: [s][128m][32k] fp16, rows 64B, swizzle q ^= (m>>1)&3  (32 KB/stage)
//   X: [s][32k][64v]  fp16, rows 128B, swizzle c ^= k&7      (16 KB/stage)
// ---------------------------------------------------------------------------
#define AS_PLANE 8192
#define A_STAGE  32768
#define XS_PLANE 4096
#define X_STAGE  16384
#define STAGE_BYTES (A_STAGE + X_STAGE)      // 49152
#define OUT_PITCH 260
#define SMEM_DYN (3 * STAGE_BYTES)           // 147456

__global__ __launch_bounds__(512, 1) void pos_map_mm(
    const float* __restrict__ token_bias, float* __restrict__ out)
{
    extern __shared__ __align__(16) char smem[];
    const int bx = blockIdx.x;
    const int m0 = (bx & 1) * 128, w = (bx >> 1) & 15, b = bx >> 5;
    const int tid = threadIdx.x, lane = tid & 31, warp = tid >> 5;
    const int wm = warp & 3;    // m-group: 32 rows
    const int wc = warp >> 2;   // s-plane
    const uint32_t sbase = smem_u32(smem);

    const __half* WgBase = g_Wgh + (size_t)(w * 4) * 65536 + (size_t)m0 * 256;
    const __half* XtBase = reinterpret_cast<const __half*>(g_Xt2)
                         + (size_t)(b * 16 + w) * 4 * 16384;

    float acc[2][8][4];
#pragma unroll
    for (int mt = 0; mt < 2; mt++)
#pragma unroll
        for (int nt = 0; nt < 8; nt++)
#pragma unroll
            for (int j = 0; j < 4; j++) acc[mt][nt][j] = 0.f;

    const int grp  = lane >> 3;
    const int row8 = (grp & 1) * 8 + (lane & 7);
    const int qsel = grp >> 1;

    auto issue_chunk = [&](int st, int ch) {
        const int n0c = ch * 32;
        // A: 2048 x 16B units (4s x 128m x 4q)
#pragma unroll
        for (int i = 0; i < 4; i++) {
            int u = tid + i * 512;
            int s = u >> 9, m = (u >> 2) & 127, q = u & 3;
            const __half* src = WgBase + s * 65536 + m * 256 + n0c + q * 8;
            uint32_t dst = sbase + st * STAGE_BYTES + s * AS_PLANE + m * 64
                         + ((q ^ ((m >> 1) & 3)) << 4);
            asm volatile("cp.async.cg.shared.global [%0], [%1], 16;"
                         :: "r"(dst), "l"(src));
        }
        // X: 1024 x 16B units (4s x 32k x 8c)
#pragma unroll
        for (int i = 0; i < 2; i++) {
            int u = tid + i * 512;
            int s = u >> 8, k = (u >> 3) & 31, c = u & 7;
            const __half* src = XtBase + s * 16384 + (n0c + k) * 64 + c * 8;
            uint32_t dst = sbase + st * STAGE_BYTES + A_STAGE + s * XS_PLANE
                         + k * 128 + ((c ^ (k & 7)) << 4);
            asm volatile("cp.async.cg.shared.global [%0], [%1], 16;"
                         :: "r"(dst), "l"(src));
        }
        asm volatile("cp.async.commit_group;");
    };

    // ---- prologue: chunks 0,1 in flight; wait for 0 only ----
    issue_chunk(0, 0);
    issue_chunk(1, 1);
    asm volatile("cp.async.wait_group 1;");
    __syncthreads();

    // ---- main loop: 8 chunks of 32 k, fully unrolled (static stage idx) ----
#pragma unroll
    for (int ch = 0; ch < 8; ch++) {
        const int st = ch % 3;
        if (ch < 6) issue_chunk((ch + 2) % 3, ch + 2);

        const uint32_t sA = sbase + st * STAGE_BYTES + wc * AS_PLANE;
        const uint32_t sX = sbase + st * STAGE_BYTES + A_STAGE + wc * XS_PLANE;
#pragma unroll
        for (int ks = 0; ks < 2; ks++) {
            uint32_t a[2][4];
#pragma unroll
            for (int mt = 0; mt < 2; mt++) {
                int m = wm * 32 + mt * 16 + row8;
                int q = ks * 2 + qsel;
                ldsm_x4(a[mt], sA + m * 64 + ((q ^ ((m >> 1) & 3)) << 4));
            }
            uint32_t bq[4][4];
#pragma unroll
            for (int ng = 0; ng < 4; ng++) {
                int k = ks * 16 + row8;
                int c = ng * 2 + qsel;
                ldsm_x4_t(bq[ng], sX + k * 128 + ((c ^ (k & 7)) << 4));
            }
#pragma unroll
            for (int mt = 0; mt < 2; mt++)
#pragma unroll
                for (int nt = 0; nt < 8; nt++)
                    hmma(acc[mt][nt], a[mt],
                         bq[nt >> 1][(nt & 1) * 2], bq[nt >> 1][(nt & 1) * 2 + 1]);
        }

        if (ch < 6)       asm volatile("cp.async.wait_group 1;");
        else if (ch == 6) asm volatile("cp.async.wait_group 0;");
        if (ch < 7) __syncthreads();
    }
    __syncthreads();

    // ---- epilogue: bias add, smem stage (reuses stages), f4 store ----
    float* so = (float*)smem;   // [128][OUT_PITCH] = 133120 B < SMEM_DYN
#pragma unroll
    for (int mt = 0; mt < 2; mt++)
#pragma unroll
        for (int j = 0; j < 2; j++) {
            int m = wm * 32 + mt * 16 + (lane >> 2) + j * 8;
            float tb = token_bias[(w * 4 + wc) * 256 + m0 + m];
            float* dr = so + m * OUT_PITCH + wc;
#pragma unroll
            for (int nt = 0; nt < 8; nt++) {
                int v = nt * 8 + ((lane & 3) << 1);
                dr[v * 4]       = acc[mt][nt][j * 2 + 0] + tb;
                dr[(v + 1) * 4] = acc[mt][nt][j * 2 + 1] + tb;
            }
        }
    __syncthreads();

    float4* ob = (float4*)(out + (size_t)((b * 16 + w) * 256 + m0) * 256);
#pragma unroll
    for (int i = 0; i < 16; i++) {
        int u = tid + i * 512;
        int row = u >> 6, c = u & 63;
        ob[row * 64 + c] = *(float4*)(so + row * OUT_PITCH + c * 4);
    }
}

// ---------------------------------------------------------------------------
// Launch: inputs in metadata order: x, bias_table, token_bias, rel_index
// ---------------------------------------------------------------------------
extern "C" void kernel_launch(void* const* d_in, const int* in_sizes, int n_in,
                              void* d_out, int out_size)
{
    const float* x          = (const float*)d_in[0];
    const float* bias_table = (const float*)d_in[1];
    const float* token_bias = (const float*)d_in[2];
    const int*   rel_index  = (const int*)d_in[3];
    float* out = (float*)d_out;
    (void)in_sizes; (void)n_in; (void)out_size;

    cudaFuncSetAttribute(pos_map_mm,
                         cudaFuncAttributeMaxDynamicSharedMemorySize, SMEM_DYN);

    prep<<<1024, 256>>>(x, bias_table, rel_index);
    pos_map_mm<<<1024, 512, SMEM_DYN>>>(token_bias, out);
}

// round 15
// speedup vs baseline: 1.0472x; 1.0142x over previous
#include <cuda_runtime.h>
#include <cuda_fp16.h>
#include <cstdint>

// ---------------------------------------------------------------------------
// Problem constants
// ---------------------------------------------------------------------------
#define B_DIM 32
#define W_DIM 16
#define N_DIM 256

// Wgh[w][s][m][n] fp16 weights (8.4 MB), L2-resident.
__device__ __half g_Wgh[W_DIM * 4 * N_DIM * N_DIM];

// ---------------------------------------------------------------------------
// Prep kernel (gather only): Wgh[w][s][m][n] = fp16(bias_table[rel_index[m][n],
// s*16+w]).  512 CTAs = (m, n-half).
// ---------------------------------------------------------------------------
__global__ __launch_bounds__(256) void build_weights(
    const float* __restrict__ bias_table, const int* __restrict__ rel_index)
{
    __shared__ float tile[128][65];
    __shared__ int rels[128];
    const int bx = blockIdx.x, tid = threadIdx.x;
    const int m = bx >> 1, n0 = (bx & 1) * 128;

    if (tid < 128) rels[tid] = rel_index[m * N_DIM + n0 + tid];
    __syncthreads();

#pragma unroll
    for (int i = 0; i < 32; i++) {
        int u = tid + i * 256;
        int n = u >> 6, c = u & 63;
        tile[n][c] = bias_table[rels[n] * 64 + c];
    }
    __syncthreads();

    __half2* g2 = reinterpret_cast<__half2*>(g_Wgh);
#pragma unroll
    for (int i = 0; i < 16; i++) {
        int u = tid + i * 256;
        int c = u >> 6, n2 = u & 63;
        int wq = c & 15, s = c >> 4;
        g2[(((wq * 4 + s) * N_DIM + m) << 7) + (n0 >> 1) + n2] =
            __floats2half2_rn(tile[2 * n2][c], tile[2 * n2 + 1][c]);
    }
}

// ---------------------------------------------------------------------------
// MMA / ldmatrix helpers
// ---------------------------------------------------------------------------
__device__ __forceinline__ void ldsm_x4(uint32_t* r, uint32_t addr) {
    asm volatile("ldmatrix.sync.aligned.m8n8.x4.shared.b16 {%0,%1,%2,%3}, [%4];"
        : "=r"(r[0]), "=r"(r[1]), "=r"(r[2]), "=r"(r[3]) : "r"(addr));
}
__device__ __forceinline__ void ldsm_x4_t(uint32_t* r, uint32_t addr) {
    asm volatile("ldmatrix.sync.aligned.m8n8.x4.trans.shared.b16 {%0,%1,%2,%3}, [%4];"
        : "=r"(r[0]), "=r"(r[1]), "=r"(r[2]), "=r"(r[3]) : "r"(addr));
}
__device__ __forceinline__ void hmma(float* d, const uint32_t* a, uint32_t b0, uint32_t b1) {
    asm volatile(
        "mma.sync.aligned.m16n8k16.row.col.f32.f16.f16.f32 "
        "{%0,%1,%2,%3},{%4,%5,%6,%7},{%8,%9},{%0,%1,%2,%3};"
        : "+f"(d[0]), "+f"(d[1]), "+f"(d[2]), "+f"(d[3])
        : "r"(a[0]), "r"(a[1]), "r"(a[2]), "r"(a[3]), "r"(b0), "r"(b1));
}
__device__ __forceinline__ uint32_t pack_h2(float lo, float hi) {
    __half2 h = __floats2half2_rn(lo, hi);
    return *reinterpret_cast<uint32_t*>(&h);
}
__device__ __forceinline__ uint32_t smem_u32(const void* p) {
    uint32_t a;
    asm("{ .reg .u64 t; cvta.to.shared.u64 t, %1; cvt.u32.u64 %0, t; }"
        : "=r"(a) : "l"(p));
    return a;
}

// ---------------------------------------------------------------------------
// Main kernel: CTA = bx -> (mh = bx&1, w = (bx>>1)&15, b = bx>>5).
// OUT tile M=128 x D=256. 512 thr. Fully unrolled 2-stage pipeline, K=32
// chunks.  A via cp.async from Wgh; X converted IN-LOOP from x fp32:
// at chunk ch, LDG x(ch+1) before compute, STS to other stage after compute.
//   A: [s][128m][32k] fp16, rows 64B, swizzle q ^= (m>>1)&3  (32 KB/stage)
//   X: [s][32k][64v]  fp16, rows 128B, swizzle c ^= k&7      (16 KB/stage)
// ---------------------------------------------------------------------------
#define AS_PLANE 8192
#define A_STAGE  32768
#define XS_PLANE 4096
#define X_STAGE  16384
#define STAGE_BYTES (A_STAGE + X_STAGE)      // 49152
#define OUT_PITCH 260
#define SMEM_DYN (128 * OUT_PITCH * 4)       // 133120 (> 2*STAGE_BYTES)

__global__ __launch_bounds__(512, 1) void pos_map_mm(
    const float* __restrict__ x, const float* __restrict__ token_bias,
    float* __restrict__ out)
{
    extern __shared__ __align__(16) char smem[];
    const int bx = blockIdx.x;
    const int m0 = (bx & 1) * 128, w = (bx >> 1) & 15, b = bx >> 5;
    const int tid = threadIdx.x, lane = tid & 31, warp = tid >> 5;
    const int wm = warp & 3;    // m-group: 32 rows
    const int wc = warp >> 2;   // s-plane
    const uint32_t sbase = smem_u32(smem);

    const __half* WgBase = g_Wgh + (size_t)(w * 4) * 65536 + (size_t)m0 * 256;
    const float4* xb4 = (const float4*)x + (size_t)(b * 16 + w) * (256 * 64);

    float acc[2][8][4];
#pragma unroll
    for (int mt = 0; mt < 2; mt++)
#pragma unroll
        for (int nt = 0; nt < 8; nt++)
#pragma unroll
            for (int j = 0; j < 4; j++) acc[mt][nt][j] = 0.f;

    const int grp  = lane >> 3;
    const int row8 = (grp & 1) * 8 + (lane & 7);
    const int qsel = grp >> 1;

    uint32_t xh[2][4];   // converted X for next chunk: [iter][s]

    auto issue_A = [&](int st, int ch) {
        const int n0c = ch * 32;
#pragma unroll
        for (int i = 0; i < 4; i++) {
            int u = tid + i * 512;                 // 2048 x 16B units
            int s = u >> 9, m = (u >> 2) & 127, q = u & 3;
            const __half* src = WgBase + s * 65536 + m * 256 + n0c + q * 8;
            uint32_t dst = sbase + st * STAGE_BYTES + s * AS_PLANE + m * 64
                         + ((q ^ ((m >> 1) & 3)) << 4);
            asm volatile("cp.async.cg.shared.global [%0], [%1], 16;"
                         :: "r"(dst), "l"(src));
        }
        asm volatile("cp.async.commit_group;");
    };
    auto load_X = [&](int ch) {
        const int n0c = ch * 32;
#pragma unroll
        for (int it = 0; it < 2; it++) {
            int u = tid + it * 512;                // 1024 (k, vpair) units
            int vp = u & 31, k = u >> 5;
            float4 f0 = xb4[(n0c + k) * 64 + 2 * vp];
            float4 f1 = xb4[(n0c + k) * 64 + 2 * vp + 1];
            const float* p0 = reinterpret_cast<const float*>(&f0);
            const float* p1 = reinterpret_cast<const float*>(&f1);
#pragma unroll
            for (int s = 0; s < 4; s++) xh[it][s] = pack_h2(p0[s], p1[s]);
        }
    };
    auto store_X = [&](int st) {
        char* xs = smem + st * STAGE_BYTES + A_STAGE;
#pragma unroll
        for (int it = 0; it < 2; it++) {
            int u = tid + it * 512;
            int vp = u & 31, k = u >> 5;
            int off = k * 128 + (((vp >> 2) ^ (k & 7)) << 4) + ((vp & 3) << 2);
#pragma unroll
            for (int s = 0; s < 4; s++)
                *(uint32_t*)(xs + s * XS_PLANE + off) = xh[it][s];
        }
    };

    // ---- prologue: chunk 0 (A via cp.async, X converted serially) ----
    issue_A(0, 0);
    load_X(0);
    store_X(0);
    asm volatile("cp.async.wait_group 0;");
    __syncthreads();

    // ---- main loop: 8 chunks of 32 k, fully unrolled ----
#pragma unroll
    for (int ch = 0; ch < 8; ch++) {
        const int st = ch & 1, nx = (ch + 1) & 1;
        if (ch < 7) {
            issue_A(nx, ch + 1);
            load_X(ch + 1);              // LDG early: latency hides under MMA
        }

        const uint32_t sA = sbase + st * STAGE_BYTES + wc * AS_PLANE;
        const uint32_t sX = sbase + st * STAGE_BYTES + A_STAGE + wc * XS_PLANE;
#pragma unroll
        for (int ks = 0; ks < 2; ks++) {
            uint32_t a[2][4];
#pragma unroll
            for (int mt = 0; mt < 2; mt++) {
                int m = wm * 32 + mt * 16 + row8;
                int q = ks * 2 + qsel;
                ldsm_x4(a[mt], sA + m * 64 + ((q ^ ((m >> 1) & 3)) << 4));
            }
            uint32_t bq[4][4];
#pragma unroll
            for (int ng = 0; ng < 4; ng++) {
                int k = ks * 16 + row8;
                int c = ng * 2 + qsel;
                ldsm_x4_t(bq[ng], sX + k * 128 + ((c ^ (k & 7)) << 4));
            }
#pragma unroll
            for (int mt = 0; mt < 2; mt++)
#pragma unroll
                for (int nt = 0; nt < 8; nt++)
                    hmma(acc[mt][nt], a[mt],
                         bq[nt >> 1][(nt & 1) * 2], bq[nt >> 1][(nt & 1) * 2 + 1]);
        }

        if (ch < 7) store_X(nx);         // STS after MMA: no stall on LDG data
        asm volatile("cp.async.wait_group 0;");
        __syncthreads();
    }

    // ---- epilogue: bias add, smem stage (reuses stages), f4 store ----
    float* so = (float*)smem;   // [128][OUT_PITCH] = 133120 B
#pragma unroll
    for (int mt = 0; mt < 2; mt++)
#pragma unroll
        for (int j = 0; j < 2; j++) {
            int m = wm * 32 + mt * 16 + (lane >> 2) + j * 8;
            float tb = token_bias[(w * 4 + wc) * 256 + m0 + m];
            float* dr = so + m * OUT_PITCH + wc;
#pragma unroll
            for (int nt = 0; nt < 8; nt++) {
                int v = nt * 8 + ((lane & 3) << 1);
                dr[v * 4]       = acc[mt][nt][j * 2 + 0] + tb;
                dr[(v + 1) * 4] = acc[mt][nt][j * 2 + 1] + tb;
            }
        }
    __syncthreads();

    float4* ob = (float4*)(out + (size_t)((b * 16 + w) * 256 + m0) * 256);
#pragma unroll
    for (int i = 0; i < 16; i++) {
        int u = tid + i * 512;
        int row = u >> 6, c = u & 63;
        ob[row * 64 + c] = *(float4*)(so + row * OUT_PITCH + c * 4);
    }
}

// ---------------------------------------------------------------------------
// Launch: inputs in metadata order: x, bias_table, token_bias, rel_index
// ---------------------------------------------------------------------------
extern "C" void kernel_launch(void* const* d_in, const int* in_sizes, int n_in,
                              void* d_out, int out_size)
{
    const float* x          = (const float*)d_in[0];
    const float* bias_table = (const float*)d_in[1];
    const float* token_bias = (const float*)d_in[2];
    const int*   rel_index  = (const int*)d_in[3];
    float* out = (float*)d_out;
    (void)in_sizes; (void)n_in; (void)out_size;

    cudaFuncSetAttribute(pos_map_mm,
                         cudaFuncAttributeMaxDynamicSharedMemorySize, SMEM_DYN);

    build_weights<<<512, 256>>>(bias_table, rel_index);
    pos_map_mm<<<1024, 512, SMEM_DYN>>>(x, token_bias, out);
}